// round 2
// baseline (speedup 1.0000x reference)
#include <cuda_runtime.h>
#include <math.h>

#define B 4096
#define D 1024
#define INV_T 20.0f   // 1 / 0.05

#define TM 128
#define TN 128
#define KC 16
#define NSPLIT 8
#define JS (B / NSPLIT)   // 512

// -------- scratch (no allocations allowed; __device__ globals) --------
__device__ float g_norm_t[B];
__device__ float g_norm_m[B];
__device__ float g_diag[B];
__device__ float g_pmax[NSPLIT][B];
__device__ float g_psum[NSPLIT][B];

// =====================================================================
// Kernel 1: per-row ||t||^2, ||m||^2, dot(t_i, m_i)
// =====================================================================
__global__ void __launch_bounds__(128) norms_kernel(const float* __restrict__ t,
                                                    const float* __restrict__ m) {
    int row = blockIdx.x;
    const float* tr = t + (size_t)row * D;
    const float* mr = m + (size_t)row * D;
    int k = threadIdx.x * 8;

    float4 t0 = *(const float4*)&tr[k];
    float4 t1 = *(const float4*)&tr[k + 4];
    float4 m0 = *(const float4*)&mr[k];
    float4 m1 = *(const float4*)&mr[k + 4];

    float st = t0.x*t0.x + t0.y*t0.y + t0.z*t0.z + t0.w*t0.w
             + t1.x*t1.x + t1.y*t1.y + t1.z*t1.z + t1.w*t1.w;
    float sm = m0.x*m0.x + m0.y*m0.y + m0.z*m0.z + m0.w*m0.w
             + m1.x*m1.x + m1.y*m1.y + m1.z*m1.z + m1.w*m1.w;
    float sd = t0.x*m0.x + t0.y*m0.y + t0.z*m0.z + t0.w*m0.w
             + t1.x*m1.x + t1.y*m1.y + t1.z*m1.z + t1.w*m1.w;

    #pragma unroll
    for (int off = 16; off > 0; off >>= 1) {
        st += __shfl_xor_sync(0xffffffffu, st, off);
        sm += __shfl_xor_sync(0xffffffffu, sm, off);
        sd += __shfl_xor_sync(0xffffffffu, sd, off);
    }
    __shared__ float sst[4], ssm[4], ssd[4];
    int warp = threadIdx.x >> 5, lane = threadIdx.x & 31;
    if (lane == 0) { sst[warp] = st; ssm[warp] = sm; ssd[warp] = sd; }
    __syncthreads();
    if (threadIdx.x == 0) {
        g_norm_t[row] = sst[0] + sst[1] + sst[2] + sst[3];
        g_norm_m[row] = ssm[0] + ssm[1] + ssm[2] + ssm[3];
        g_diag[row]   = ssd[0] + ssd[1] + ssd[2] + ssd[3];
    }
}

// =====================================================================
// Kernel 2: fused SGEMM + per-row online logsumexp (diag excluded)
// grid = (B/TM, NSPLIT), block = 256 threads, 8x8 per thread
// =====================================================================
__global__ void __launch_bounds__(256, 2) gemm_lse(const float* __restrict__ Tm,
                                                   const float* __restrict__ Mm) {
    __shared__ float As[KC][TM + 4];
    __shared__ float Bs[KC][TN + 4];
    __shared__ float s_rmax[TM];
    __shared__ float s_rsum[TM];

    const int tid = threadIdx.x;
    const int tx  = tid & 15;       // 0..15 -> j sub-block
    const int ty  = tid >> 4;       // 0..15 -> i sub-block
    const int i0  = blockIdx.x * TM;
    const int s   = blockIdx.y;

    for (int r = tid; r < TM; r += 256) { s_rmax[r] = -INFINITY; s_rsum[r] = 0.0f; }

    const int lrow = tid >> 1;          // 0..127
    const int lseg = (tid & 1) * 8;     // 0 or 8

    for (int jt = 0; jt < JS / TN; jt++) {
        const int j0 = s * JS + jt * TN;

        float acc[8][8];
        #pragma unroll
        for (int r = 0; r < 8; r++)
            #pragma unroll
            for (int c = 0; c < 8; c++) acc[r][c] = 0.0f;

        for (int k0 = 0; k0 < D; k0 += KC) {
            float4 a0 = *(const float4*)&Tm[(size_t)(i0 + lrow) * D + k0 + lseg];
            float4 a1 = *(const float4*)&Tm[(size_t)(i0 + lrow) * D + k0 + lseg + 4];
            float4 b0 = *(const float4*)&Mm[(size_t)(j0 + lrow) * D + k0 + lseg];
            float4 b1 = *(const float4*)&Mm[(size_t)(j0 + lrow) * D + k0 + lseg + 4];
            __syncthreads();
            As[lseg + 0][lrow] = a0.x; As[lseg + 1][lrow] = a0.y;
            As[lseg + 2][lrow] = a0.z; As[lseg + 3][lrow] = a0.w;
            As[lseg + 4][lrow] = a1.x; As[lseg + 5][lrow] = a1.y;
            As[lseg + 6][lrow] = a1.z; As[lseg + 7][lrow] = a1.w;
            Bs[lseg + 0][lrow] = b0.x; Bs[lseg + 1][lrow] = b0.y;
            Bs[lseg + 2][lrow] = b0.z; Bs[lseg + 3][lrow] = b0.w;
            Bs[lseg + 4][lrow] = b1.x; Bs[lseg + 5][lrow] = b1.y;
            Bs[lseg + 6][lrow] = b1.z; Bs[lseg + 7][lrow] = b1.w;
            __syncthreads();

            #pragma unroll
            for (int k = 0; k < KC; k++) {
                float4 va0 = *(const float4*)&As[k][ty * 8];
                float4 va1 = *(const float4*)&As[k][ty * 8 + 4];
                float4 vb0 = *(const float4*)&Bs[k][tx * 8];
                float4 vb1 = *(const float4*)&Bs[k][tx * 8 + 4];
                float a[8] = {va0.x, va0.y, va0.z, va0.w, va1.x, va1.y, va1.z, va1.w};
                float b[8] = {vb0.x, vb0.y, vb0.z, vb0.w, vb1.x, vb1.y, vb1.z, vb1.w};
                #pragma unroll
                for (int r = 0; r < 8; r++)
                    #pragma unroll
                    for (int c = 0; c < 8; c++)
                        acc[r][c] = fmaf(a[r], b[c], acc[r][c]);
            }
        }

        // ---- epilogue: logits + row logsumexp over this 128-j tile ----
        float nmv[8];
        #pragma unroll
        for (int c = 0; c < 8; c++) nmv[c] = g_norm_m[j0 + tx * 8 + c];

        #pragma unroll
        for (int r = 0; r < 8; r++) {
            const int gi = i0 + ty * 8 + r;
            const float ntr = g_norm_t[gi];
            float l[8];
            float lm = -INFINITY;
            #pragma unroll
            for (int c = 0; c < 8; c++) {
                const int gj = j0 + tx * 8 + c;
                float dsq = ntr + nmv[c] - 2.0f * acc[r][c];
                float dd  = sqrtf(fmaxf(dsq, 0.0f));
                float lg  = (gi == gj) ? -INFINITY : (-dd * INV_T);
                l[c] = lg;
                lm = fmaxf(lm, lg);
            }
            float ls = 0.0f;
            #pragma unroll
            for (int c = 0; c < 8; c++) ls += __expf(l[c] - lm);

            // reduce across the 16 lanes owning this row (same ty, tx varies)
            #pragma unroll
            for (int off = 8; off > 0; off >>= 1) {
                float om = __shfl_xor_sync(0xffffffffu, lm, off, 16);
                float os = __shfl_xor_sync(0xffffffffu, ls, off, 16);
                float nx = fmaxf(lm, om);
                ls = ls * __expf(lm - nx) + os * __expf(om - nx);
                lm = nx;
            }
            if (tx == 0) {
                const int row = ty * 8 + r;
                float om = s_rmax[row], os = s_rsum[row];
                float nx = fmaxf(om, lm);
                // om may be -inf on first tile: os==0 so 0*__expf(-inf)=0 is fine
                s_rsum[row] = os * __expf(om - nx) + ls * __expf(lm - nx);
                s_rmax[row] = nx;
            }
        }
    }

    __syncthreads();
    if (tid < TM) {
        g_pmax[s][i0 + tid] = s_rmax[tid];
        g_psum[s][i0 + tid] = s_rsum[tid];
    }
}

// =====================================================================
// Kernel 3: merge split partials, add diag term, mean -> scalar
// =====================================================================
__global__ void __launch_bounds__(256) finalize_kernel(float* __restrict__ out) {
    __shared__ float red[256];
    float acc = 0.0f;
    for (int i = threadIdx.x; i < B; i += 256) {
        float gm = -INFINITY;
        #pragma unroll
        for (int s = 0; s < NSPLIT; s++) gm = fmaxf(gm, g_pmax[s][i]);
        float gs = 0.0f;
        #pragma unroll
        for (int s = 0; s < NSPLIT; s++) gs += g_psum[s][i] * __expf(g_pmax[s][i] - gm);
        float lse = gm + logf(gs);
        float dsq = g_norm_t[i] + g_norm_m[i] - 2.0f * g_diag[i];
        float dii = sqrtf(fmaxf(dsq, 0.0f));
        acc += lse + dii * INV_T;
    }
    red[threadIdx.x] = acc;
    __syncthreads();
    #pragma unroll
    for (int off = 128; off > 0; off >>= 1) {
        if (threadIdx.x < off) red[threadIdx.x] += red[threadIdx.x + off];
        __syncthreads();
    }
    if (threadIdx.x == 0) out[0] = red[0] / (float)B;
}

// =====================================================================
extern "C" void kernel_launch(void* const* d_in, const int* in_sizes, int n_in,
                              void* d_out, int out_size) {
    const float* t = (const float*)d_in[0];
    const float* m = (const float*)d_in[1];
    (void)in_sizes; (void)n_in; (void)out_size;

    norms_kernel<<<B, 128>>>(t, m);
    gemm_lse<<<dim3(B / TM, NSPLIT), 256>>>(t, m);
    finalize_kernel<<<1, 256>>>((float*)d_out);
}

// round 4
// speedup vs baseline: 3.0529x; 3.0529x over previous
#include <cuda_runtime.h>
#include <math.h>
#include <stdint.h>

#define B 4096
#define D 1024
#define INV_T 20.0f
#define LOG2E 1.4426950408889634f
#define LN2 0.6931471805599453f
#define SHIFT 96.0f

#define TM 128
#define TN 128
#define KC 32
#define NIT (D / KC)          // 32
#define NSPLIT (B / TN)       // 32
#define LDSS 36               // smem row stride in floats (conflict-free fragments)
#define TILE_F (128 * LDSS)   // floats per (A or B) buffer

// -------- scratch --------
__device__ float g_norm_t[B];
__device__ float g_norm_m[B];
__device__ float g_diag[B];
__device__ float g_psum[NSPLIT][B];

// round fp32 -> tf32 (round-half-up on bit 12, then truncate low 13 bits)
__device__ __forceinline__ float rnd_tf32(float x) {
    uint32_t u = __float_as_uint(x);
    u = (u + 0x1000u) & 0xFFFFE000u;
    return __uint_as_float(u);
}

__device__ __forceinline__ void mma_tf32(float* d, const uint32_t* a, const uint32_t* b) {
    asm volatile(
        "mma.sync.aligned.m16n8k8.row.col.f32.tf32.tf32.f32 "
        "{%0,%1,%2,%3}, {%4,%5,%6,%7}, {%8,%9}, {%0,%1,%2,%3};"
        : "+f"(d[0]), "+f"(d[1]), "+f"(d[2]), "+f"(d[3])
        : "r"(a[0]), "r"(a[1]), "r"(a[2]), "r"(a[3]), "r"(b[0]), "r"(b[1]));
}

// ==================== Kernel 1: norms + diag ====================
__global__ void __launch_bounds__(128) norms_kernel(const float* __restrict__ t,
                                                    const float* __restrict__ m) {
    int row = blockIdx.x;
    const float* tr = t + (size_t)row * D;
    const float* mr = m + (size_t)row * D;
    int k = threadIdx.x * 8;

    float4 t0 = *(const float4*)&tr[k];
    float4 t1 = *(const float4*)&tr[k + 4];
    float4 m0 = *(const float4*)&mr[k];
    float4 m1 = *(const float4*)&mr[k + 4];

    float st = t0.x*t0.x + t0.y*t0.y + t0.z*t0.z + t0.w*t0.w
             + t1.x*t1.x + t1.y*t1.y + t1.z*t1.z + t1.w*t1.w;
    float sm = m0.x*m0.x + m0.y*m0.y + m0.z*m0.z + m0.w*m0.w
             + m1.x*m1.x + m1.y*m1.y + m1.z*m1.z + m1.w*m1.w;
    float sd = t0.x*m0.x + t0.y*m0.y + t0.z*m0.z + t0.w*m0.w
             + t1.x*m1.x + t1.y*m1.y + t1.z*m1.z + t1.w*m1.w;

    #pragma unroll
    for (int off = 16; off > 0; off >>= 1) {
        st += __shfl_xor_sync(0xffffffffu, st, off);
        sm += __shfl_xor_sync(0xffffffffu, sm, off);
        sd += __shfl_xor_sync(0xffffffffu, sd, off);
    }
    __shared__ float sst[4], ssm[4], ssd[4];
    int warp = threadIdx.x >> 5, lane = threadIdx.x & 31;
    if (lane == 0) { sst[warp] = st; ssm[warp] = sm; ssd[warp] = sd; }
    __syncthreads();
    if (threadIdx.x == 0) {
        g_norm_t[row] = sst[0] + sst[1] + sst[2] + sst[3];
        g_norm_m[row] = ssm[0] + ssm[1] + ssm[2] + ssm[3];
        g_diag[row]   = ssd[0] + ssd[1] + ssd[2] + ssd[3];
    }
}

// ==================== Kernel 2: mma.sync tf32 GEMM + fused LSE-sum ====================
__global__ void __launch_bounds__(256)
gemm_lse(const float* __restrict__ Tm, const float* __restrict__ Mm) {
    extern __shared__ float sh[];
    float* As[2] = { sh,              sh + TILE_F };
    float* Bs[2] = { sh + 2 * TILE_F, sh + 3 * TILE_F };
    __shared__ float s_nt[TM], s_nm[TN], s_row[TM];

    const int tid = threadIdx.x;
    const int w = tid >> 5, lane = tid & 31;
    const int wm = w & 1, wn = w >> 1;          // 2 M-warps x 4 N-warps
    const int g = lane >> 2, tq = lane & 3;     // fragment group / quad
    const int i0 = blockIdx.x * TM;
    const int j0 = blockIdx.y * TN;

    if (tid < TM) {
        s_row[tid] = 0.0f;
        s_nt[tid] = g_norm_t[i0 + tid];
        s_nm[tid] = g_norm_m[j0 + tid];
    }

    // per-thread global-load slots: 4 float4 for A, 4 for B per stage
    const int lr  = tid >> 3;                   // 0..31 (row within group of 32 per p-step)
    const int seg = tid & 7;                    // 0..7  (16B segment in 128B row)
    float4 pa[4], pb[4];

    #pragma unroll
    for (int p = 0; p < 4; p++) {
        int r = lr + p * 32;
        pa[p] = *(const float4*)&Tm[(size_t)(i0 + r) * D + seg * 4];
        pb[p] = *(const float4*)&Mm[(size_t)(j0 + r) * D + seg * 4];
    }

    float acc[4][4][4];
    #pragma unroll
    for (int mt = 0; mt < 4; mt++)
        #pragma unroll
        for (int nt = 0; nt < 4; nt++)
            #pragma unroll
            for (int q = 0; q < 4; q++) acc[mt][nt][q] = 0.0f;

    // store stage 0
    #pragma unroll
    for (int p = 0; p < 4; p++) {
        int r = lr + p * 32;
        float4 va = make_float4(rnd_tf32(pa[p].x), rnd_tf32(pa[p].y),
                                rnd_tf32(pa[p].z), rnd_tf32(pa[p].w));
        float4 vb = make_float4(rnd_tf32(pb[p].x), rnd_tf32(pb[p].y),
                                rnd_tf32(pb[p].z), rnd_tf32(pb[p].w));
        *(float4*)&As[0][r * LDSS + seg * 4] = va;
        *(float4*)&Bs[0][r * LDSS + seg * 4] = vb;
    }
    __syncthreads();

    for (int it = 0; it < NIT; it++) {
        const int buf = it & 1;
        if (it + 1 < NIT) {
            const int k0 = (it + 1) * KC;
            #pragma unroll
            for (int p = 0; p < 4; p++) {
                int r = lr + p * 32;
                pa[p] = *(const float4*)&Tm[(size_t)(i0 + r) * D + k0 + seg * 4];
                pb[p] = *(const float4*)&Mm[(size_t)(j0 + r) * D + k0 + seg * 4];
            }
        }

        const float* Ab = As[buf];
        const float* Bb = Bs[buf];
        #pragma unroll
        for (int ks = 0; ks < 4; ks++) {
            const int kb = ks * 8 + tq;
            uint32_t af[4][4], bf[4][2];
            #pragma unroll
            for (int mt = 0; mt < 4; mt++) {
                const int base = (wm * 64 + mt * 16 + g) * LDSS + kb;
                af[mt][0] = __float_as_uint(Ab[base]);
                af[mt][1] = __float_as_uint(Ab[base + 8 * LDSS]);
                af[mt][2] = __float_as_uint(Ab[base + 4]);
                af[mt][3] = __float_as_uint(Ab[base + 8 * LDSS + 4]);
            }
            #pragma unroll
            for (int nt = 0; nt < 4; nt++) {
                const int base = (wn * 32 + nt * 8 + g) * LDSS + kb;
                bf[nt][0] = __float_as_uint(Bb[base]);
                bf[nt][1] = __float_as_uint(Bb[base + 4]);
            }
            #pragma unroll
            for (int mt = 0; mt < 4; mt++)
                #pragma unroll
                for (int nt = 0; nt < 4; nt++)
                    mma_tf32(acc[mt][nt], af[mt], bf[nt]);
        }
        __syncthreads();

        if (it + 1 < NIT) {
            const int nb = buf ^ 1;
            #pragma unroll
            for (int p = 0; p < 4; p++) {
                int r = lr + p * 32;
                float4 va = make_float4(rnd_tf32(pa[p].x), rnd_tf32(pa[p].y),
                                        rnd_tf32(pa[p].z), rnd_tf32(pa[p].w));
                float4 vb = make_float4(rnd_tf32(pb[p].x), rnd_tf32(pb[p].y),
                                        rnd_tf32(pb[p].z), rnd_tf32(pb[p].w));
                *(float4*)&As[nb][r * LDSS + seg * 4] = va;
                *(float4*)&Bs[nb][r * LDSS + seg * 4] = vb;
            }
            __syncthreads();
        }
    }

    // ---- epilogue: logits -> shifted exp2 -> row sums ----
    const float C = -INV_T * LOG2E;
    #pragma unroll
    for (int mt = 0; mt < 4; mt++) {
        #pragma unroll
        for (int rh = 0; rh < 2; rh++) {
            const int row = wm * 64 + mt * 16 + g + rh * 8;
            const int gi = i0 + row;
            const float nt_ = s_nt[row];
            float rs = 0.0f;
            #pragma unroll
            for (int nt = 0; nt < 4; nt++) {
                #pragma unroll
                for (int cc = 0; cc < 2; cc++) {
                    const int col = wn * 32 + nt * 8 + tq * 2 + cc;
                    const float a = acc[mt][nt][rh * 2 + cc];
                    float dsq = fmaxf(fmaf(-2.0f, a, nt_ + s_nm[col]), 1e-20f);
                    float rsq; asm("rsqrt.approx.f32 %0, %1;" : "=f"(rsq) : "f"(dsq));
                    float dd = dsq * rsq;                       // sqrt
                    float x = fmaf(dd, C, SHIFT);
                    float e; asm("ex2.approx.f32 %0, %1;" : "=f"(e) : "f"(x));
                    rs += ((j0 + col) == gi) ? 0.0f : e;
                }
            }
            rs += __shfl_xor_sync(0xffffffffu, rs, 1);
            rs += __shfl_xor_sync(0xffffffffu, rs, 2);
            if (tq == 0) atomicAdd(&s_row[row], rs);
        }
    }
    __syncthreads();
    if (tid < TM) g_psum[blockIdx.y][i0 + tid] = s_row[tid];
}

// ==================== Kernel 3: finalize ====================
__global__ void __launch_bounds__(256) finalize_kernel(float* __restrict__ out) {
    __shared__ float red[256];
    float acc = 0.0f;
    for (int i = threadIdx.x; i < B; i += 256) {
        float S = 0.0f;
        #pragma unroll
        for (int s = 0; s < NSPLIT; s++) S += g_psum[s][i];
        float lse = logf(S) - SHIFT * LN2;
        float dsq = g_norm_t[i] + g_norm_m[i] - 2.0f * g_diag[i];
        float dii = sqrtf(fmaxf(dsq, 0.0f));
        acc += lse + dii * INV_T;
    }
    red[threadIdx.x] = acc;
    __syncthreads();
    #pragma unroll
    for (int off = 128; off > 0; off >>= 1) {
        if (threadIdx.x < off) red[threadIdx.x] += red[threadIdx.x + off];
        __syncthreads();
    }
    if (threadIdx.x == 0) out[0] = red[0] / (float)B;
}

// ==================== launch ====================
extern "C" void kernel_launch(void* const* d_in, const int* in_sizes, int n_in,
                              void* d_out, int out_size) {
    const float* t = (const float*)d_in[0];
    const float* m = (const float*)d_in[1];
    (void)in_sizes; (void)n_in; (void)out_size;

    const int dyn = 4 * TILE_F * sizeof(float);  // 73,728 B
    cudaFuncSetAttribute(gemm_lse, cudaFuncAttributeMaxDynamicSharedMemorySize, dyn);

    norms_kernel<<<B, 128>>>(t, m);
    gemm_lse<<<dim3(B / TM, B / TN), 256, dyn>>>(t, m);
    finalize_kernel<<<1, 256>>>((float*)d_out);
}

// round 5
// speedup vs baseline: 6.2705x; 2.0539x over previous
#include <cuda_runtime.h>
#include <cuda_bf16.h>
#include <math.h>
#include <stdint.h>

#define B 4096
#define D 1024
#define INV_T 20.0f
#define LOG2E 1.4426950408889634f
#define LN2 0.6931471805599453f
#define SHIFT 96.0f

#define TM 128
#define TN 128
#define KC 32                  // K elements per stage
#define NIT (D / KC)           // 32
#define NSTAGE 3
#define NSPLIT (B / TN)        // 32
#define PITCH 40               // bf16 per smem row (80 B, conflict-free ldmatrix)
#define MAT_BYTES (128 * PITCH * 2)      // 10240
#define STAGE_BYTES (2 * MAT_BYTES)      // 20480
#define DYN_SMEM (NSTAGE * STAGE_BYTES)  // 61440

// -------- scratch --------
__device__ float g_norm_t[B];
__device__ float g_norm_m[B];
__device__ float g_diag[B];
__device__ float g_psum[NSPLIT][B];
__device__ __nv_bfloat16 g_tb[B * D];
__device__ __nv_bfloat16 g_mb[B * D];

__device__ __forceinline__ uint32_t smem_u32(const void* p) {
    uint32_t a;
    asm("{ .reg .u64 t; cvta.to.shared.u64 t, %1; cvt.u32.u64 %0, t; }" : "=r"(a) : "l"(p));
    return a;
}
__device__ __forceinline__ void cp_async16(uint32_t dst, const void* src) {
    asm volatile("cp.async.cg.shared.global [%0], [%1], 16;\n" :: "r"(dst), "l"(src));
}
__device__ __forceinline__ void ldsm_x4(uint32_t* r, uint32_t addr) {
    asm volatile("ldmatrix.sync.aligned.m8n8.x4.shared.b16 {%0,%1,%2,%3}, [%4];"
                 : "=r"(r[0]), "=r"(r[1]), "=r"(r[2]), "=r"(r[3]) : "r"(addr));
}
__device__ __forceinline__ void mma_bf16(float* d, const uint32_t* a, const uint32_t* b) {
    asm volatile(
        "mma.sync.aligned.m16n8k16.row.col.f32.bf16.bf16.f32 "
        "{%0,%1,%2,%3}, {%4,%5,%6,%7}, {%8,%9}, {%0,%1,%2,%3};"
        : "+f"(d[0]), "+f"(d[1]), "+f"(d[2]), "+f"(d[3])
        : "r"(a[0]), "r"(a[1]), "r"(a[2]), "r"(a[3]), "r"(b[0]), "r"(b[1]));
}
__device__ __forceinline__ uint32_t pack_bf2(float x, float y) {
    __nv_bfloat162 v = __floats2bfloat162_rn(x, y);
    return *(uint32_t*)&v;
}

// ==================== Kernel 1: norms + diag + bf16 convert ====================
__global__ void __launch_bounds__(128) norms_kernel(const float* __restrict__ t,
                                                    const float* __restrict__ m) {
    int row = blockIdx.x;
    const float* tr = t + (size_t)row * D;
    const float* mr = m + (size_t)row * D;
    int k = threadIdx.x * 8;

    float4 t0 = *(const float4*)&tr[k];
    float4 t1 = *(const float4*)&tr[k + 4];
    float4 m0 = *(const float4*)&mr[k];
    float4 m1 = *(const float4*)&mr[k + 4];

    uint4 tb = make_uint4(pack_bf2(t0.x, t0.y), pack_bf2(t0.z, t0.w),
                          pack_bf2(t1.x, t1.y), pack_bf2(t1.z, t1.w));
    uint4 mb = make_uint4(pack_bf2(m0.x, m0.y), pack_bf2(m0.z, m0.w),
                          pack_bf2(m1.x, m1.y), pack_bf2(m1.z, m1.w));
    *(uint4*)&g_tb[(size_t)row * D + k] = tb;
    *(uint4*)&g_mb[(size_t)row * D + k] = mb;

    float st = t0.x*t0.x + t0.y*t0.y + t0.z*t0.z + t0.w*t0.w
             + t1.x*t1.x + t1.y*t1.y + t1.z*t1.z + t1.w*t1.w;
    float sm = m0.x*m0.x + m0.y*m0.y + m0.z*m0.z + m0.w*m0.w
             + m1.x*m1.x + m1.y*m1.y + m1.z*m1.z + m1.w*m1.w;
    float sd = t0.x*m0.x + t0.y*m0.y + t0.z*m0.z + t0.w*m0.w
             + t1.x*m1.x + t1.y*m1.y + t1.z*m1.z + t1.w*m1.w;

    #pragma unroll
    for (int off = 16; off > 0; off >>= 1) {
        st += __shfl_xor_sync(0xffffffffu, st, off);
        sm += __shfl_xor_sync(0xffffffffu, sm, off);
        sd += __shfl_xor_sync(0xffffffffu, sd, off);
    }
    __shared__ float sst[4], ssm[4], ssd[4];
    int warp = threadIdx.x >> 5, lane = threadIdx.x & 31;
    if (lane == 0) { sst[warp] = st; ssm[warp] = sm; ssd[warp] = sd; }
    __syncthreads();
    if (threadIdx.x == 0) {
        g_norm_t[row] = sst[0] + sst[1] + sst[2] + sst[3];
        g_norm_m[row] = ssm[0] + ssm[1] + ssm[2] + ssm[3];
        g_diag[row]   = ssd[0] + ssd[1] + ssd[2] + ssd[3];
    }
}

// ==================== Kernel 2: bf16 mma GEMM + fused LSE-sum ====================
__device__ __forceinline__ void load_stage(uint32_t aBase, uint32_t bBase,
                                           int i0, int j0, int k0, int tid) {
    // A: 128 rows x 4 segs of 8 bf16 (16B); B same. 512 chunks each; 2 per thread.
    #pragma unroll
    for (int p = 0; p < 2; p++) {
        int c = tid + p * 256;
        int r = c >> 2, s = c & 3;
        cp_async16(aBase + r * (PITCH * 2) + s * 16,
                   g_tb + (size_t)(i0 + r) * D + k0 + s * 8);
        cp_async16(bBase + r * (PITCH * 2) + s * 16,
                   g_mb + (size_t)(j0 + r) * D + k0 + s * 8);
    }
    asm volatile("cp.async.commit_group;\n" ::: "memory");
}

__global__ void __launch_bounds__(256, 2)
gemm_lse(const float* __restrict__ dummy) {
    extern __shared__ char dsm[];
    __shared__ float s_nt[TM], s_nm[TN], s_row[TM];

    const int tid = threadIdx.x;
    const int w = tid >> 5, lane = tid & 31;
    const int wm = w & 1, wn = w >> 1;          // 2 M-warps x 4 N-warps
    const int g = lane >> 2, tq = lane & 3;
    const int i0 = blockIdx.x * TM;
    const int j0 = blockIdx.y * TN;

    const uint32_t sbase = smem_u32(dsm);

    if (tid < TM) {
        s_row[tid] = 0.0f;
        s_nt[tid] = g_norm_t[i0 + tid];
        s_nm[tid] = g_norm_m[j0 + tid];
    }

    // ldmatrix per-lane offsets (bytes)
    const int rA = (lane & 7) + ((lane >> 3) & 1) * 8;
    const uint32_t offA = rA * (PITCH * 2) + (lane >> 4) * 16;
    const int rB = (lane & 7) + ((lane >> 4) & 1) * 8;
    const uint32_t offB = rB * (PITCH * 2) + ((lane >> 3) & 1) * 16;

    float acc[4][4][4];
    #pragma unroll
    for (int mt = 0; mt < 4; mt++)
        #pragma unroll
        for (int nt = 0; nt < 4; nt++)
            #pragma unroll
            for (int q = 0; q < 4; q++) acc[mt][nt][q] = 0.0f;

    // prologue: stages 0,1
    load_stage(sbase, sbase + MAT_BYTES, i0, j0, 0, tid);
    load_stage(sbase + STAGE_BYTES, sbase + STAGE_BYTES + MAT_BYTES, i0, j0, KC, tid);

    for (int it = 0; it < NIT; it++) {
        asm volatile("cp.async.wait_group 1;\n" ::: "memory");
        __syncthreads();

        if (it + 2 < NIT) {
            const uint32_t nb = sbase + ((it + 2) % NSTAGE) * STAGE_BYTES;
            load_stage(nb, nb + MAT_BYTES, i0, j0, (it + 2) * KC, tid);
        } else {
            asm volatile("cp.async.commit_group;\n" ::: "memory");
        }

        const uint32_t aS = sbase + (it % NSTAGE) * STAGE_BYTES;
        const uint32_t bS = aS + MAT_BYTES;

        #pragma unroll
        for (int ks = 0; ks < 2; ks++) {              // two k16 steps
            const uint32_t kb = ks * 32;              // 16 bf16 = 32 bytes
            uint32_t af[4][4], bf_[4][4];
            #pragma unroll
            for (int mt = 0; mt < 4; mt++)
                ldsm_x4(af[mt], aS + (wm * 64 + mt * 16) * (PITCH * 2) + kb + offA);
            #pragma unroll
            for (int np = 0; np < 2; np++)
                ldsm_x4(bf_[np * 2], bS + (wn * 32 + np * 16) * (PITCH * 2) + kb + offB);
            // bf_[np*2] = {b0,b1 of tile np*2, b0,b1 of tile np*2+1}
            #pragma unroll
            for (int mt = 0; mt < 4; mt++) {
                #pragma unroll
                for (int nt = 0; nt < 4; nt++) {
                    const uint32_t* bp = &bf_[(nt >> 1) * 2][(nt & 1) * 2];
                    mma_bf16(acc[mt][nt], af[mt], bp);
                }
            }
        }
    }

    // ---- epilogue: logits -> shifted exp2 -> row sums ----
    const float C = -INV_T * LOG2E;
    #pragma unroll
    for (int mt = 0; mt < 4; mt++) {
        #pragma unroll
        for (int rh = 0; rh < 2; rh++) {
            const int row = wm * 64 + mt * 16 + g + rh * 8;
            const int gi = i0 + row;
            const float nt_ = s_nt[row];
            float rs = 0.0f;
            #pragma unroll
            for (int nt = 0; nt < 4; nt++) {
                #pragma unroll
                for (int cc = 0; cc < 2; cc++) {
                    const int col = wn * 32 + nt * 8 + tq * 2 + cc;
                    const float a = acc[mt][nt][rh * 2 + cc];
                    float dsq = fmaxf(fmaf(-2.0f, a, nt_ + s_nm[col]), 1e-20f);
                    float rsq; asm("rsqrt.approx.f32 %0, %1;" : "=f"(rsq) : "f"(dsq));
                    float dd = dsq * rsq;
                    float x = fmaf(dd, C, SHIFT);
                    float e; asm("ex2.approx.f32 %0, %1;" : "=f"(e) : "f"(x));
                    rs += ((j0 + col) == gi) ? 0.0f : e;
                }
            }
            rs += __shfl_xor_sync(0xffffffffu, rs, 1);
            rs += __shfl_xor_sync(0xffffffffu, rs, 2);
            if (tq == 0) atomicAdd(&s_row[row], rs);
        }
    }
    __syncthreads();
    if (tid < TM) g_psum[blockIdx.y][i0 + tid] = s_row[tid];
}

// ==================== Kernel 3: finalize ====================
__global__ void __launch_bounds__(256) finalize_kernel(float* __restrict__ out) {
    __shared__ float red[256];
    float acc = 0.0f;
    for (int i = threadIdx.x; i < B; i += 256) {
        float S = 0.0f;
        #pragma unroll
        for (int s = 0; s < NSPLIT; s++) S += g_psum[s][i];
        float lse = logf(S) - SHIFT * LN2;
        float dsq = g_norm_t[i] + g_norm_m[i] - 2.0f * g_diag[i];
        float dii = sqrtf(fmaxf(dsq, 0.0f));
        acc += lse + dii * INV_T;
    }
    red[threadIdx.x] = acc;
    __syncthreads();
    #pragma unroll
    for (int off = 128; off > 0; off >>= 1) {
        if (threadIdx.x < off) red[threadIdx.x] += red[threadIdx.x + off];
        __syncthreads();
    }
    if (threadIdx.x == 0) out[0] = red[0] / (float)B;
}

// ==================== launch ====================
extern "C" void kernel_launch(void* const* d_in, const int* in_sizes, int n_in,
                              void* d_out, int out_size) {
    const float* t = (const float*)d_in[0];
    const float* m = (const float*)d_in[1];
    (void)in_sizes; (void)n_in; (void)out_size;

    cudaFuncSetAttribute(gemm_lse, cudaFuncAttributeMaxDynamicSharedMemorySize, DYN_SMEM);

    norms_kernel<<<B, 128>>>(t, m);
    gemm_lse<<<dim3(B / TM, B / TN), 256, DYN_SMEM>>>(t);
    finalize_kernel<<<1, 256>>>((float*)d_out);
}

// round 6
// speedup vs baseline: 7.8594x; 1.2534x over previous
#include <cuda_runtime.h>
#include <cuda_bf16.h>
#include <math.h>
#include <stdint.h>

#define B 4096
#define D 1024
#define INV_T 20.0f
#define LOG2E 1.4426950408889634f
#define LN2 0.6931471805599453f
#define SHIFT 96.0f

#define TM 128
#define TN 128
#define KC 64                  // K elements per stage
#define NIT (D / KC)           // 16
#define NSTAGE 3
#define NSPLIT (B / TN)        // 32
#define PITCH 72               // bf16 per smem row (144 B, conflict-free)
#define ROWB (PITCH * 2)       // 144
#define MAT_BYTES (128 * ROWB)           // 18432
#define STAGE_BYTES (2 * MAT_BYTES)      // 36864
#define DYN_SMEM (NSTAGE * STAGE_BYTES)  // 110592
#define NFIN 16

// -------- scratch --------
__device__ float g_norm_t[B];
__device__ float g_norm_m[B];
__device__ float g_diag[B];
__device__ float g_psum[NSPLIT][B];
__device__ float g_fin[NFIN];
__device__ __nv_bfloat16 g_tb[B * D];
__device__ __nv_bfloat16 g_mb[B * D];

__device__ __forceinline__ uint32_t smem_u32(const void* p) {
    uint32_t a;
    asm("{ .reg .u64 t; cvta.to.shared.u64 t, %1; cvt.u32.u64 %0, t; }" : "=r"(a) : "l"(p));
    return a;
}
__device__ __forceinline__ void cp_async16(uint32_t dst, const void* src) {
    asm volatile("cp.async.cg.shared.global [%0], [%1], 16;\n" :: "r"(dst), "l"(src));
}
__device__ __forceinline__ void ldsm_x4(uint32_t* r, uint32_t addr) {
    asm volatile("ldmatrix.sync.aligned.m8n8.x4.shared.b16 {%0,%1,%2,%3}, [%4];"
                 : "=r"(r[0]), "=r"(r[1]), "=r"(r[2]), "=r"(r[3]) : "r"(addr));
}
__device__ __forceinline__ void mma_bf16(float* d, const uint32_t* a, const uint32_t* b) {
    asm volatile(
        "mma.sync.aligned.m16n8k16.row.col.f32.bf16.bf16.f32 "
        "{%0,%1,%2,%3}, {%4,%5,%6,%7}, {%8,%9}, {%0,%1,%2,%3};"
        : "+f"(d[0]), "+f"(d[1]), "+f"(d[2]), "+f"(d[3])
        : "r"(a[0]), "r"(a[1]), "r"(a[2]), "r"(a[3]), "r"(b[0]), "r"(b[1]));
}
__device__ __forceinline__ uint32_t pack_bf2(float x, float y) {
    __nv_bfloat162 v = __floats2bfloat162_rn(x, y);
    return *(uint32_t*)&v;
}

// ==================== Kernel 1: norms + diag + bf16 convert ====================
__global__ void __launch_bounds__(128) norms_kernel(const float* __restrict__ t,
                                                    const float* __restrict__ m) {
    int row = blockIdx.x;
    const float* tr = t + (size_t)row * D;
    const float* mr = m + (size_t)row * D;
    int k = threadIdx.x * 8;

    float4 t0 = *(const float4*)&tr[k];
    float4 t1 = *(const float4*)&tr[k + 4];
    float4 m0 = *(const float4*)&mr[k];
    float4 m1 = *(const float4*)&mr[k + 4];

    uint4 tb = make_uint4(pack_bf2(t0.x, t0.y), pack_bf2(t0.z, t0.w),
                          pack_bf2(t1.x, t1.y), pack_bf2(t1.z, t1.w));
    uint4 mb = make_uint4(pack_bf2(m0.x, m0.y), pack_bf2(m0.z, m0.w),
                          pack_bf2(m1.x, m1.y), pack_bf2(m1.z, m1.w));
    *(uint4*)&g_tb[(size_t)row * D + k] = tb;
    *(uint4*)&g_mb[(size_t)row * D + k] = mb;

    float st = t0.x*t0.x + t0.y*t0.y + t0.z*t0.z + t0.w*t0.w
             + t1.x*t1.x + t1.y*t1.y + t1.z*t1.z + t1.w*t1.w;
    float sm = m0.x*m0.x + m0.y*m0.y + m0.z*m0.z + m0.w*m0.w
             + m1.x*m1.x + m1.y*m1.y + m1.z*m1.z + m1.w*m1.w;
    float sd = t0.x*m0.x + t0.y*m0.y + t0.z*m0.z + t0.w*m0.w
             + t1.x*m1.x + t1.y*m1.y + t1.z*m1.z + t1.w*m1.w;

    #pragma unroll
    for (int off = 16; off > 0; off >>= 1) {
        st += __shfl_xor_sync(0xffffffffu, st, off);
        sm += __shfl_xor_sync(0xffffffffu, sm, off);
        sd += __shfl_xor_sync(0xffffffffu, sd, off);
    }
    __shared__ float sst[4], ssm[4], ssd[4];
    int warp = threadIdx.x >> 5, lane = threadIdx.x & 31;
    if (lane == 0) { sst[warp] = st; ssm[warp] = sm; ssd[warp] = sd; }
    __syncthreads();
    if (threadIdx.x == 0) {
        g_norm_t[row] = sst[0] + sst[1] + sst[2] + sst[3];
        g_norm_m[row] = ssm[0] + ssm[1] + ssm[2] + ssm[3];
        g_diag[row]   = ssd[0] + ssd[1] + ssd[2] + ssd[3];
    }
}

// ==================== Kernel 2: bf16 mma GEMM + fused LSE-sum ====================
__device__ __forceinline__ void load_stage(uint32_t aBase, uint32_t bBase,
                                           int i0, int j0, int k0, int tid) {
    // stage = 128 rows x 128B (8 chunks of 16B) each for A and B; 4 chunks/thread each
    #pragma unroll
    for (int p = 0; p < 4; p++) {
        int c = tid + p * 256;
        int r = c >> 3, s = c & 7;
        cp_async16(aBase + r * ROWB + s * 16,
                   g_tb + (size_t)(i0 + r) * D + k0 + s * 8);
        cp_async16(bBase + r * ROWB + s * 16,
                   g_mb + (size_t)(j0 + r) * D + k0 + s * 8);
    }
    asm volatile("cp.async.commit_group;\n" ::: "memory");
}

__global__ void __launch_bounds__(256, 2)
gemm_lse(const float* __restrict__ dummy) {
    extern __shared__ char dsm[];
    __shared__ float s_nt[TM], s_nm[TN], s_row[TM];

    const int tid = threadIdx.x;
    const int w = tid >> 5, lane = tid & 31;
    const int wm = w & 1, wn = w >> 1;          // 2 M-warps x 4 N-warps
    const int g = lane >> 2, tq = lane & 3;
    const int i0 = blockIdx.x * TM;
    const int j0 = blockIdx.y * TN;

    const uint32_t sbase = smem_u32(dsm);

    if (tid < TM) {
        s_row[tid] = 0.0f;
        s_nt[tid] = g_norm_t[i0 + tid];
        s_nm[tid] = g_norm_m[j0 + tid];
    }

    // ldmatrix per-lane offsets (bytes)
    const int rA = (lane & 7) + ((lane >> 3) & 1) * 8;
    const uint32_t offA = rA * ROWB + (lane >> 4) * 16;
    const int rB = (lane & 7) + ((lane >> 4) & 1) * 8;
    const uint32_t offB = rB * ROWB + ((lane >> 3) & 1) * 16;

    float acc[4][4][4];
    #pragma unroll
    for (int mt = 0; mt < 4; mt++)
        #pragma unroll
        for (int nt = 0; nt < 4; nt++)
            #pragma unroll
            for (int q = 0; q < 4; q++) acc[mt][nt][q] = 0.0f;

    // prologue: stages 0,1
    load_stage(sbase, sbase + MAT_BYTES, i0, j0, 0, tid);
    load_stage(sbase + STAGE_BYTES, sbase + STAGE_BYTES + MAT_BYTES, i0, j0, KC, tid);

    for (int it = 0; it < NIT; it++) {
        asm volatile("cp.async.wait_group 1;\n" ::: "memory");
        __syncthreads();

        if (it + 2 < NIT) {
            const uint32_t nb = sbase + ((it + 2) % NSTAGE) * STAGE_BYTES;
            load_stage(nb, nb + MAT_BYTES, i0, j0, (it + 2) * KC, tid);
        } else {
            asm volatile("cp.async.commit_group;\n" ::: "memory");
        }

        const uint32_t aS = sbase + (it % NSTAGE) * STAGE_BYTES;
        const uint32_t bS = aS + MAT_BYTES;

        #pragma unroll
        for (int ks = 0; ks < 4; ks++) {              // four k16 steps
            const uint32_t kb = ks * 32;              // 16 bf16 = 32 bytes
            uint32_t af[4][4], bf_[4][4];
            #pragma unroll
            for (int mt = 0; mt < 4; mt++)
                ldsm_x4(af[mt], aS + (wm * 64 + mt * 16) * ROWB + kb + offA);
            #pragma unroll
            for (int np = 0; np < 2; np++)
                ldsm_x4(bf_[np * 2], bS + (wn * 32 + np * 16) * ROWB + kb + offB);
            #pragma unroll
            for (int mt = 0; mt < 4; mt++) {
                #pragma unroll
                for (int nt = 0; nt < 4; nt++) {
                    const uint32_t* bp = &bf_[(nt >> 1) * 2][(nt & 1) * 2];
                    mma_bf16(acc[mt][nt], af[mt], bp);
                }
            }
        }
    }

    // ---- epilogue: logits -> shifted exp2 -> row sums ----
    const float C = -INV_T * LOG2E;
    #pragma unroll
    for (int mt = 0; mt < 4; mt++) {
        #pragma unroll
        for (int rh = 0; rh < 2; rh++) {
            const int row = wm * 64 + mt * 16 + g + rh * 8;
            const int gi = i0 + row;
            const float nt_ = s_nt[row];
            float rs = 0.0f;
            #pragma unroll
            for (int nt = 0; nt < 4; nt++) {
                #pragma unroll
                for (int cc = 0; cc < 2; cc++) {
                    const int col = wn * 32 + nt * 8 + tq * 2 + cc;
                    const float a = acc[mt][nt][rh * 2 + cc];
                    float dsq = fmaxf(fmaf(-2.0f, a, nt_ + s_nm[col]), 1e-20f);
                    float rsq; asm("rsqrt.approx.f32 %0, %1;" : "=f"(rsq) : "f"(dsq));
                    float dd = dsq * rsq;
                    float x = fmaf(dd, C, SHIFT);
                    float e; asm("ex2.approx.f32 %0, %1;" : "=f"(e) : "f"(x));
                    rs += ((j0 + col) == gi) ? 0.0f : e;
                }
            }
            rs += __shfl_xor_sync(0xffffffffu, rs, 1);
            rs += __shfl_xor_sync(0xffffffffu, rs, 2);
            if (tq == 0) atomicAdd(&s_row[row], rs);
        }
    }
    __syncthreads();
    if (tid < TM) g_psum[blockIdx.y][i0 + tid] = s_row[tid];
}

// ==================== Kernel 3a/3b: finalize ====================
__global__ void __launch_bounds__(256) finalize1_kernel() {
    __shared__ float red[256];
    const int i = blockIdx.x * 256 + threadIdx.x;   // one row per thread
    float S = 0.0f;
    #pragma unroll
    for (int s = 0; s < NSPLIT; s++) S += g_psum[s][i];
    float lse = logf(S) - SHIFT * LN2;
    float dsq = g_norm_t[i] + g_norm_m[i] - 2.0f * g_diag[i];
    float dii = sqrtf(fmaxf(dsq, 0.0f));
    red[threadIdx.x] = lse + dii * INV_T;
    __syncthreads();
    #pragma unroll
    for (int off = 128; off > 0; off >>= 1) {
        if (threadIdx.x < off) red[threadIdx.x] += red[threadIdx.x + off];
        __syncthreads();
    }
    if (threadIdx.x == 0) g_fin[blockIdx.x] = red[0];
}

__global__ void __launch_bounds__(32) finalize2_kernel(float* __restrict__ out) {
    float v = (threadIdx.x < NFIN) ? g_fin[threadIdx.x] : 0.0f;
    #pragma unroll
    for (int off = 16; off > 0; off >>= 1) v += __shfl_xor_sync(0xffffffffu, v, off);
    if (threadIdx.x == 0) out[0] = v / (float)B;
}

// ==================== launch ====================
extern "C" void kernel_launch(void* const* d_in, const int* in_sizes, int n_in,
                              void* d_out, int out_size) {
    const float* t = (const float*)d_in[0];
    const float* m = (const float*)d_in[1];
    (void)in_sizes; (void)n_in; (void)out_size;

    cudaFuncSetAttribute(gemm_lse, cudaFuncAttributeMaxDynamicSharedMemorySize, DYN_SMEM);

    norms_kernel<<<B, 128>>>(t, m);
    gemm_lse<<<dim3(B / TM, B / TN), 256, DYN_SMEM>>>(t);
    finalize1_kernel<<<NFIN, 256>>>();
    finalize2_kernel<<<1, 32>>>((float*)d_out);
}